// round 5
// baseline (speedup 1.0000x reference)
#include <cuda_runtime.h>

#define HWSZ (512*512)
typedef unsigned long long u64;

__device__ __forceinline__ float ex2f(float x) {
    float r; asm("ex2.approx.f32 %0, %1;" : "=f"(r) : "f"(x)); return r;
}
__device__ __forceinline__ float rcpf(float x) {
    float r; asm("rcp.approx.f32 %0, %1;" : "=f"(r) : "f"(x)); return r;
}
__device__ __forceinline__ u64 pk(float a, float b) {
    u64 r; asm("mov.b64 %0, {%1,%2};" : "=l"(r) : "f"(a), "f"(b)); return r;
}
__device__ __forceinline__ u64 mul2(u64 a, u64 b) {
    u64 r; asm("mul.rn.f32x2 %0, %1, %2;" : "=l"(r) : "l"(a), "l"(b)); return r;
}
__device__ __forceinline__ u64 fma2(u64 a, u64 b, u64 c) {
    u64 r; asm("fma.rn.f32x2 %0, %1, %2, %3;" : "=l"(r) : "l"(a), "l"(b), "l"(c)); return r;
}
__device__ __forceinline__ u64 add2(u64 a, u64 b) {
    u64 r; asm("add.rn.f32x2 %0, %1, %2;" : "=l"(r) : "l"(a), "l"(b)); return r;
}

// Tile: 32 wide x 16 tall outputs, 64 threads (32x2), 8 output rows/thread.
// Halo tile: 26 rows x 42 cols.
__global__ __launch_bounds__(64, 12) void GaussPSF_kernel(
    const float* __restrict__ img,
    const float* __restrict__ psf,
    float* __restrict__ out)
{
    // (c0,c1,c2,u) per halo pixel, u = exp2(-log2e/(2*w^2+eps))
    __shared__ float4 tile[26 * 42];

    const int tx = threadIdx.x;           // 0..31
    const int ty = threadIdx.y;           // 0..1
    const int tid = ty * 32 + tx;
    const int x0 = blockIdx.x * 32;
    const int y0 = blockIdx.y * 16;
    const int b  = blockIdx.z;

    const float* imb = img + (size_t)b * 3 * HWSZ;
    const float* psb = psf + (size_t)b * HWSZ;

    // ---- stage halo tile (EX2/RCP once per site) ----
    for (int i = tid; i < 26 * 42; i += 64) {
        int sy = i / 42;
        int sx = i - sy * 42;
        int gy = y0 - 5 + sy;
        int gx = x0 - 5 + sx;
        float4 r;
        if ((unsigned)gy < 512u && (unsigned)gx < 512u) {
            int p = gy * 512 + gx;
            r.x = imb[p];
            r.y = imb[HWSZ + p];
            r.z = imb[2 * HWSZ + p];
            float w = psb[p];
            float t = fmaf(w + w, w, 1e-5f);                 // 2w^2 + eps
            r.w = ex2f(-1.4426950408889634f * rcpf(t));      // u
        } else {
            r.x = 0.f; r.y = 0.f; r.z = 0.f;
            r.w = 0.f;                                        // mask: powers -> 0
        }
        tile[i] = r;
    }
    __syncthreads();

    // ---- 8 outputs per thread: rows y0 + ty*8 + (0..7), column x0 + tx ----
    u64 a01[8], a2w[8];   // f32x2 accumulators: (out0,out1), (out2,wsum)
    #pragma unroll
    for (int o = 0; o < 8; ++o) { a01[o] = 0ull; a2w[o] = 0ull; }

    const int rowbase = ty * 8;

    #pragma unroll
    for (int s = 0; s < 18; ++s) {            // shared row = rowbase + s
        const int base = (rowbase + s) * 42 + tx;
        float4 r = tile[base];                // prefetch j=0
        #pragma unroll
        for (int j = 0; j < 11; ++j) {
            float4 nxt;
            if (j < 10) nxt = tile[base + j + 1];

            // power chain on packed {u,u} pairs (depth 5)
            u64 p1  = pk(r.w, r.w);           // u^1
            u64 t2  = mul2(p1, p1);           // u^2
            u64 q4  = mul2(t2, t2);           // u^4
            u64 t8  = mul2(q4, q4);           // u^8
            u64 q9  = mul2(t8, p1);           // u^9
            u64 q16 = mul2(t8, t8);           // u^16
            u64 q25 = mul2(q16, q9);          // u^25

            u64 P[6];
            P[1] = p1; P[2] = q4; P[3] = q9; P[4] = q16; P[5] = q25;

            const int dxa = (j < 5) ? (5 - j) : (j - 5);
            u64 c01 = pk(r.x, r.y);
            u64 c2w = pk(r.z, 1.0f);
            if (dxa != 0) {
                c01 = mul2(c01, P[dxa]);
                c2w = mul2(c2w, P[dxa]);
            }

            #pragma unroll
            for (int o = 0; o < 8; ++o) {
                const int dy  = s - 5 - o;     // compile-time after unroll
                const int dya = (dy < 0) ? -dy : dy;
                if (dya <= 5) {
                    if (dya == 0) {
                        a01[o] = add2(a01[o], c01);
                        a2w[o] = add2(a2w[o], c2w);
                    } else {
                        a01[o] = fma2(c01, P[dya], a01[o]);
                        a2w[o] = fma2(c2w, P[dya], a2w[o]);
                    }
                }
            }
            r = nxt;
        }
    }

    // ---- normalize & write ----
    float* ob = out + (size_t)b * 3 * HWSZ;
    #pragma unroll
    for (int o = 0; o < 8; ++o) {
        float o0, o1, o2, ws;
        asm("mov.b64 {%0,%1}, %2;" : "=f"(o0), "=f"(o1) : "l"(a01[o]));
        asm("mov.b64 {%0,%1}, %2;" : "=f"(o2), "=f"(ws) : "l"(a2w[o]));
        float rw = rcpf(ws);
        int y = y0 + rowbase + o;
        int p = y * 512 + x0 + tx;
        ob[p]            = o0 * rw;
        ob[HWSZ + p]     = o1 * rw;
        ob[2 * HWSZ + p] = o2 * rw;
    }
}

extern "C" void kernel_launch(void* const* d_in, const int* in_sizes, int n_in,
                              void* d_out, int out_size)
{
    const float* img = (const float*)d_in[0];   // (4,3,512,512) f32
    const float* psf = (const float*)d_in[1];   // (4,512,512)   f32
    float* out = (float*)d_out;                 // (4,3,512,512) f32

    dim3 block(32, 2, 1);
    dim3 grid(512 / 32, 512 / 16, 4);
    GaussPSF_kernel<<<grid, block>>>(img, psf, out);
}

// round 6
// speedup vs baseline: 1.2723x; 1.2723x over previous
#include <cuda_runtime.h>

#define HWSZ (512*512)
#define HALO (42*42)
typedef unsigned long long u64;

__device__ __forceinline__ float ex2f(float x) {
    float r; asm("ex2.approx.f32 %0, %1;" : "=f"(r) : "f"(x)); return r;
}
__device__ __forceinline__ float rcpf(float x) {
    float r; asm("rcp.approx.f32 %0, %1;" : "=f"(r) : "f"(x)); return r;
}
__device__ __forceinline__ u64 pk(float a, float b) {
    u64 r; asm("mov.b64 %0, {%1,%2};" : "=l"(r) : "f"(a), "f"(b)); return r;
}
__device__ __forceinline__ u64 mul2(u64 a, u64 b) {
    u64 r; asm("mul.rn.f32x2 %0, %1, %2;" : "=l"(r) : "l"(a), "l"(b)); return r;
}
__device__ __forceinline__ u64 fma2(u64 a, u64 b, u64 c) {
    u64 r; asm("fma.rn.f32x2 %0, %1, %2, %3;" : "=l"(r) : "l"(a), "l"(b), "l"(c)); return r;
}
__device__ __forceinline__ u64 add2(u64 a, u64 b) {
    u64 r; asm("add.rn.f32x2 %0, %1, %2;" : "=l"(r) : "l"(a), "l"(b)); return r;
}

// Tile: 32x32 outputs, block (32,4)=128 threads, 8 output rows/thread.
// Shared: per halo site two float4s: tc=(c0,c1,c2,u), tp=(u^4,u^9,u^16,u^25).
// Powers computed ONCE per site at staging (instead of per consuming thread).
__global__ __launch_bounds__(128, 4) void GaussPSF_kernel(
    const float* __restrict__ img,
    const float* __restrict__ psf,
    float* __restrict__ out)
{
    extern __shared__ float4 sh[];
    float4* tc = sh;            // channels + u
    float4* tp = sh + HALO;     // u^4, u^9, u^16, u^25

    const int tx = threadIdx.x;           // 0..31
    const int ty = threadIdx.y;           // 0..3
    const int tid = ty * 32 + tx;
    const int x0 = blockIdx.x * 32;
    const int y0 = blockIdx.y * 32;
    const int b  = blockIdx.z;

    const float* imb = img + (size_t)b * 3 * HWSZ;
    const float* psb = psf + (size_t)b * HWSZ;

    // ---- stage halo tile: EX2/RCP and FULL power chain once per site ----
    for (int i = tid; i < HALO; i += 128) {
        int sy = i / 42;
        int sx = i - sy * 42;
        int gy = y0 - 5 + sy;
        int gx = x0 - 5 + sx;
        float4 rc, rp;
        if ((unsigned)gy < 512u && (unsigned)gx < 512u) {
            int p = gy * 512 + gx;
            rc.x = imb[p];
            rc.y = imb[HWSZ + p];
            rc.z = imb[2 * HWSZ + p];
            float w = psb[p];
            float t  = fmaf(w + w, w, 1e-5f);                 // 2w^2 + eps
            float u  = ex2f(-1.4426950408889634f * rcpf(t));  // u
            float u2 = u * u;
            float u4 = u2 * u2;
            float u8 = u4 * u4;
            float u9 = u8 * u;
            float u16 = u8 * u8;
            float u25 = u16 * u9;
            rc.w = u;
            rp.x = u4; rp.y = u9; rp.z = u16; rp.w = u25;
        } else {
            rc.x = 0.f; rc.y = 0.f; rc.z = 0.f; rc.w = 0.f;
            rp.x = 0.f; rp.y = 0.f; rp.z = 0.f; rp.w = 0.f;  // mask
        }
        tc[i] = rc;
        tp[i] = rp;
    }
    __syncthreads();

    // ---- 8 outputs per thread: rows y0 + ty*8 + (0..7), column x0 + tx ----
    u64 a01[8], a2w[8];   // f32x2 accumulators: (out0,out1), (out2,wsum)
    #pragma unroll
    for (int o = 0; o < 8; ++o) { a01[o] = 0ull; a2w[o] = 0ull; }

    const int rowbase = ty * 8;

    #pragma unroll
    for (int s = 0; s < 18; ++s) {            // shared row = rowbase + s
        const int base = (rowbase + s) * 42 + tx;
        float4 rc = tc[base];                 // prefetch j=0
        float4 rpw = tp[base];
        #pragma unroll
        for (int j = 0; j < 11; ++j) {
            float4 nc, np;
            if (j < 10) { nc = tc[base + j + 1]; np = tp[base + j + 1]; }

            // broadcast-pack powers (ALU pipe; no fma chain anymore)
            u64 P[6];
            P[1] = pk(rc.w,  rc.w);
            P[2] = pk(rpw.x, rpw.x);
            P[3] = pk(rpw.y, rpw.y);
            P[4] = pk(rpw.z, rpw.z);
            P[5] = pk(rpw.w, rpw.w);

            const int dxa = (j < 5) ? (5 - j) : (j - 5);
            u64 c01 = pk(rc.x, rc.y);
            u64 c2w = pk(rc.z, 1.0f);
            if (dxa != 0) {
                c01 = mul2(c01, P[dxa]);
                c2w = mul2(c2w, P[dxa]);
            }

            #pragma unroll
            for (int o = 0; o < 8; ++o) {
                const int dy  = s - 5 - o;     // compile-time after unroll
                const int dya = (dy < 0) ? -dy : dy;
                if (dya <= 5) {
                    if (dya == 0) {
                        a01[o] = add2(a01[o], c01);
                        a2w[o] = add2(a2w[o], c2w);
                    } else {
                        a01[o] = fma2(c01, P[dya], a01[o]);
                        a2w[o] = fma2(c2w, P[dya], a2w[o]);
                    }
                }
            }
            rc = nc; rpw = np;
        }
    }

    // ---- normalize & write ----
    float* ob = out + (size_t)b * 3 * HWSZ;
    #pragma unroll
    for (int o = 0; o < 8; ++o) {
        float o0, o1, o2, ws;
        asm("mov.b64 {%0,%1}, %2;" : "=f"(o0), "=f"(o1) : "l"(a01[o]));
        asm("mov.b64 {%0,%1}, %2;" : "=f"(o2), "=f"(ws) : "l"(a2w[o]));
        float rw = rcpf(ws);
        int y = y0 + rowbase + o;
        int p = y * 512 + x0 + tx;
        ob[p]            = o0 * rw;
        ob[HWSZ + p]     = o1 * rw;
        ob[2 * HWSZ + p] = o2 * rw;
    }
}

extern "C" void kernel_launch(void* const* d_in, const int* in_sizes, int n_in,
                              void* d_out, int out_size)
{
    const float* img = (const float*)d_in[0];   // (4,3,512,512) f32
    const float* psf = (const float*)d_in[1];   // (4,512,512)   f32
    float* out = (float*)d_out;                 // (4,3,512,512) f32

    const int smem = HALO * 2 * (int)sizeof(float4);   // 56448 B
    cudaFuncSetAttribute(GaussPSF_kernel,
                         cudaFuncAttributeMaxDynamicSharedMemorySize, smem);

    dim3 block(32, 4, 1);
    dim3 grid(512 / 32, 512 / 32, 4);
    GaussPSF_kernel<<<grid, block, smem>>>(img, psf, out);
}

// round 7
// speedup vs baseline: 1.3542x; 1.0643x over previous
#include <cuda_runtime.h>

#define HWSZ (512*512)
#define HALO (42*42)
typedef unsigned long long u64;

__device__ __forceinline__ float ex2f(float x) {
    float r; asm("ex2.approx.f32 %0, %1;" : "=f"(r) : "f"(x)); return r;
}
__device__ __forceinline__ float rcpf(float x) {
    float r; asm("rcp.approx.f32 %0, %1;" : "=f"(r) : "f"(x)); return r;
}
__device__ __forceinline__ u64 pk(float a, float b) {
    u64 r; asm("mov.b64 %0, {%1,%2};" : "=l"(r) : "f"(a), "f"(b)); return r;
}
__device__ __forceinline__ u64 mul2(u64 a, u64 b) {
    u64 r; asm("mul.rn.f32x2 %0, %1, %2;" : "=l"(r) : "l"(a), "l"(b)); return r;
}
__device__ __forceinline__ u64 fma2(u64 a, u64 b, u64 c) {
    u64 r; asm("fma.rn.f32x2 %0, %1, %2, %3;" : "=l"(r) : "l"(a), "l"(b), "l"(c)); return r;
}
__device__ __forceinline__ u64 add2(u64 a, u64 b) {
    u64 r; asm("add.rn.f32x2 %0, %1, %2;" : "=l"(r) : "l"(a), "l"(b)); return r;
}

// Tile 32x32 outputs, block (32,4)=128 thr, 8 output rows/thread.
// Shared per halo site:
//   tA = (c0, c1, c2, 1.0f)  -> loaded as ulonglong2: c01 / c2w pairs, no packs
//   tB = (u, u^4, u^9, u^16) -> u^25 = u^9*u^16 at consumer (1 scalar mul)
__global__ __launch_bounds__(128, 4) void GaussPSF_kernel(
    const float* __restrict__ img,
    const float* __restrict__ psf,
    float* __restrict__ out)
{
    extern __shared__ float4 sh[];
    float4* tA = sh;                 // HALO + 1 (pad for unconditional prefetch)
    float4* tB = sh + (HALO + 1);    // HALO + 1

    const int tx = threadIdx.x;           // 0..31
    const int ty = threadIdx.y;           // 0..3
    const int tid = ty * 32 + tx;
    const int x0 = blockIdx.x * 32;
    const int y0 = blockIdx.y * 32;
    const int b  = blockIdx.z;

    const float* imb = img + (size_t)b * 3 * HWSZ;
    const float* psb = psf + (size_t)b * HWSZ;

    // ---- stage halo: EX2/RCP + power chain once per site ----
    for (int i = tid; i < HALO; i += 128) {
        int sy = i / 42;
        int sx = i - sy * 42;
        int gy = y0 - 5 + sy;
        int gx = x0 - 5 + sx;
        float4 ra, rb;
        if ((unsigned)gy < 512u && (unsigned)gx < 512u) {
            int p = gy * 512 + gx;
            ra.x = imb[p];
            ra.y = imb[HWSZ + p];
            ra.z = imb[2 * HWSZ + p];
            ra.w = 1.0f;                                      // wsum rides here
            float w = psb[p];
            float t  = fmaf(w + w, w, 1e-5f);                 // 2w^2 + eps
            float u  = ex2f(-1.4426950408889634f * rcpf(t));  // u
            float u2 = u * u;
            float u4 = u2 * u2;
            float u8 = u4 * u4;
            rb.x = u;
            rb.y = u4;
            rb.z = u8 * u;        // u^9
            rb.w = u8 * u8;       // u^16
        } else {
            ra.x = 0.f; ra.y = 0.f; ra.z = 0.f; ra.w = 0.f;   // taps vanish
            rb.x = 0.f; rb.y = 0.f; rb.z = 0.f; rb.w = 0.f;   // powers -> 0
        }
        tA[i] = ra;
        tB[i] = rb;
    }
    __syncthreads();

    const ulonglong2* tA64 = reinterpret_cast<const ulonglong2*>(tA);

    // ---- 8 outputs per thread: rows y0 + ty*8 + (0..7), column x0 + tx ----
    u64 a01[8], a2w[8];
    #pragma unroll
    for (int o = 0; o < 8; ++o) { a01[o] = 0ull; a2w[o] = 0ull; }

    const int rowbase = ty * 8;

    #pragma unroll
    for (int s = 0; s < 18; ++s) {            // shared row = rowbase + s
        const int base = (rowbase + s) * 42 + tx;
        ulonglong2 av = tA64[base];           // prefetch j=0
        float4     bv = tB[base];
        #pragma unroll
        for (int j = 0; j < 11; ++j) {
            // unconditional prefetch (arrays padded by 1 site)
            ulonglong2 an = tA64[base + j + 1];
            float4     bn = tB[base + j + 1];

            // broadcast pairs (unused ones are DCE'd per unrolled (s,j))
            u64 P[6];
            P[1] = pk(bv.x, bv.x);
            P[2] = pk(bv.y, bv.y);
            P[3] = pk(bv.z, bv.z);
            P[4] = pk(bv.w, bv.w);
            float u25 = bv.z * bv.w;
            P[5] = pk(u25, u25);

            const int dxa = (j < 5) ? (5 - j) : (j - 5);
            u64 c01 = av.x;                   // (c0,c1) — direct from LDS.128
            u64 c2w = av.y;                   // (c2,1.0)
            if (dxa != 0) {
                c01 = mul2(c01, P[dxa]);
                c2w = mul2(c2w, P[dxa]);
            }

            #pragma unroll
            for (int o = 0; o < 8; ++o) {
                const int dy  = s - 5 - o;     // compile-time after unroll
                const int dya = (dy < 0) ? -dy : dy;
                if (dya <= 5) {
                    if (dya == 0) {
                        a01[o] = add2(a01[o], c01);
                        a2w[o] = add2(a2w[o], c2w);
                    } else {
                        a01[o] = fma2(c01, P[dya], a01[o]);
                        a2w[o] = fma2(c2w, P[dya], a2w[o]);
                    }
                }
            }
            av = an; bv = bn;
        }
    }

    // ---- normalize & write ----
    float* ob = out + (size_t)b * 3 * HWSZ;
    #pragma unroll
    for (int o = 0; o < 8; ++o) {
        float o0, o1, o2, ws;
        asm("mov.b64 {%0,%1}, %2;" : "=f"(o0), "=f"(o1) : "l"(a01[o]));
        asm("mov.b64 {%0,%1}, %2;" : "=f"(o2), "=f"(ws) : "l"(a2w[o]));
        float rw = rcpf(ws);
        int y = y0 + rowbase + o;
        int p = y * 512 + x0 + tx;
        ob[p]            = o0 * rw;
        ob[HWSZ + p]     = o1 * rw;
        ob[2 * HWSZ + p] = o2 * rw;
    }
}

extern "C" void kernel_launch(void* const* d_in, const int* in_sizes, int n_in,
                              void* d_out, int out_size)
{
    const float* img = (const float*)d_in[0];   // (4,3,512,512) f32
    const float* psf = (const float*)d_in[1];   // (4,512,512)   f32
    float* out = (float*)d_out;                 // (4,3,512,512) f32

    const int smem = (2 * HALO + 2) * (int)sizeof(float4);   // 56480 B
    cudaFuncSetAttribute(GaussPSF_kernel,
                         cudaFuncAttributeMaxDynamicSharedMemorySize, smem);

    dim3 block(32, 4, 1);
    dim3 grid(512 / 32, 512 / 32, 4);
    GaussPSF_kernel<<<grid, block, smem>>>(img, psf, out);
}